// round 7
// baseline (speedup 1.0000x reference)
#include <cuda_runtime.h>

#define TPB 256
typedef unsigned long long u64;

namespace {
constexpr int NODE = 112;
constexpr int XP   = 116;   // x tile pitch (floats)
constexpr int HP   = 260;   // H buffer pitch (256 cols max)
constexpr int TPT  = 68;    // T (h1 block) pitch, 64 cols
constexpr int GP3  = 132;   // g3 pitch (128 cols)
constexpr int TP2  = 68;    // g4 pitch (64 cols)
constexpr int SMEM_FLOATS = NODE*XP + NODE*HP + NODE*GP3 + 256;
constexpr int SMEM_BYTES  = SMEM_FLOATS * 4;   // 228,608 B
}

__device__ __forceinline__ u64 pk2(float lo, float hi) {
    u64 r;
    asm("mov.b64 %0,{%1,%2};" : "=l"(r)
        : "r"(__float_as_uint(lo)), "r"(__float_as_uint(hi)));
    return r;
}
__device__ __forceinline__ void fma2(u64& d, u64 a, u64 b) {
    asm("fma.rn.f32x2 %0,%1,%2,%0;" : "+l"(d) : "l"(a), "l"(b));
}
__device__ __forceinline__ float2 up2(u64 p) {
    unsigned lo, hi;
    asm("mov.b64 {%0,%1},%2;" : "=r"(lo), "=r"(hi) : "l"(p));
    return make_float2(__uint_as_float(lo), __uint_as_float(hi));
}
__device__ __forceinline__ float frelu(float v) { return v > 0.f ? v : 0.f; }

__global__ __launch_bounds__(TPB, 1) void gcn_fused(
    const float* __restrict__ x,
    const float* __restrict__ W1, const float* __restrict__ b1,
    const float* __restrict__ W2, const float* __restrict__ b2,
    const float* __restrict__ W3, const float* __restrict__ b3,
    const float* __restrict__ W4, const float* __restrict__ b4,
    const float* __restrict__ W5, const float* __restrict__ b5,
    const float* __restrict__ Wf, const float* __restrict__ bf,
    float* __restrict__ out)
{
    extern __shared__ float sm[];
    float* xs  = sm;                    // [112][116]
    float* Hb  = sm + NODE*XP;          // [112][260]
    float* Gb  = Hb + NODE*HP;          // [112][132]  (T pitch 68 / g3 pitch 132 / g4 pitch 68)
    float* g5  = Gb + NODE*GP3;         // [112]
    float* red = g5 + NODE;             // [112]

    const int tid  = threadIdx.x;
    const int bidx = blockIdx.x;
    const int tr = tid & 15;
    const int tc = tid >> 4;
    const int m0 = tr * 7;

    // ---------------- stage 0: load x tile -------------------------------------
    {
        const float4* xg = reinterpret_cast<const float4*>(x + (size_t)bidx * NODE * NODE);
        #pragma unroll 4
        for (int i = tid; i < NODE * 28; i += TPB) {
            int r = i / 28, c = i - r * 28;
            *reinterpret_cast<float4*>(&xs[r*XP + c*4]) = xg[i];
        }
    }
    __syncthreads();

    // ---------------- stage 1: fused layer1 -> g2 = h1 @ W2^T ------------------
    // cb blocks of 64 h1-columns; T = relu(x@W1_blk^T + b1_blk) in Gb; g2 RMW in Hb.
    #pragma unroll 1
    for (int cb = 0; cb < 4; cb++) {
        const int c0 = cb * 64;
        // (a) T[112,64] block
        {
            const int d = c0 + tc * 4;
            const float* w0 = W1 + (size_t)d * NODE;
            const float* w1 = w0 + NODE;
            const float* w2 = w0 + 2*NODE;
            const float* w3 = w0 + 3*NODE;
            u64 a0[7], a1[7];
            {
                u64 bi0 = pk2(b1[d], b1[d+1]);
                u64 bi1 = pk2(b1[d+2], b1[d+3]);
                #pragma unroll
                for (int i = 0; i < 7; i++) { a0[i] = bi0; a1[i] = bi1; }
            }
            #pragma unroll 1
            for (int k = 0; k < NODE; k += 4) {
                float4 v0 = *reinterpret_cast<const float4*>(w0 + k);
                float4 v1 = *reinterpret_cast<const float4*>(w1 + k);
                float4 v2 = *reinterpret_cast<const float4*>(w2 + k);
                float4 v3 = *reinterpret_cast<const float4*>(w3 + k);
                u64 p00 = pk2(v0.x, v1.x), p01 = pk2(v0.y, v1.y);
                u64 p02 = pk2(v0.z, v1.z), p03 = pk2(v0.w, v1.w);
                u64 p10 = pk2(v2.x, v3.x), p11 = pk2(v2.y, v3.y);
                u64 p12 = pk2(v2.z, v3.z), p13 = pk2(v2.w, v3.w);
                #pragma unroll
                for (int i = 0; i < 7; i++) {
                    float4 xv = *reinterpret_cast<const float4*>(&xs[(m0+i)*XP + k]);
                    u64 dx = pk2(xv.x, xv.x);
                    u64 dy = pk2(xv.y, xv.y);
                    u64 dz = pk2(xv.z, xv.z);
                    u64 dw = pk2(xv.w, xv.w);
                    fma2(a0[i], dx, p00); fma2(a1[i], dx, p10);
                    fma2(a0[i], dy, p01); fma2(a1[i], dy, p11);
                    fma2(a0[i], dz, p02); fma2(a1[i], dz, p12);
                    fma2(a0[i], dw, p03); fma2(a1[i], dw, p13);
                }
            }
            #pragma unroll
            for (int i = 0; i < 7; i++) {
                float2 u = up2(a0[i]), v = up2(a1[i]);
                float* t = &Gb[(m0+i)*TPT + tc*4];
                t[0] = frelu(u.x); t[1] = frelu(u.y);
                t[2] = frelu(v.x); t[3] = frelu(v.y);
            }
        }
        __syncthreads();
        // (b) g2[:, d0:d0+16] += T @ W2[:, c0:c0+64]^T
        {
            const int d0 = tc * 16;
            u64 acc[7][8];
            if (cb == 0) {
                #pragma unroll
                for (int i = 0; i < 7; i++)
                    #pragma unroll
                    for (int jp = 0; jp < 8; jp++) acc[i][jp] = 0ULL;
            } else {
                #pragma unroll
                for (int i = 0; i < 7; i++) {
                    const u64* hr = reinterpret_cast<const u64*>(&Hb[(m0+i)*HP + d0]);
                    #pragma unroll
                    for (int jp = 0; jp < 8; jp++) acc[i][jp] = hr[jp];
                }
            }
            #pragma unroll 1
            for (int kk = 0; kk < 64; kk += 2) {
                u64 bp[8][2];
                #pragma unroll
                for (int jp = 0; jp < 8; jp++) {
                    const float* wa = W2 + (size_t)(d0 + 2*jp) * 256 + c0 + kk;
                    const float* wb = wa + 256;
                    float2 a = *reinterpret_cast<const float2*>(wa);
                    float2 b = *reinterpret_cast<const float2*>(wb);
                    bp[jp][0] = pk2(a.x, b.x);
                    bp[jp][1] = pk2(a.y, b.y);
                }
                #pragma unroll
                for (int i = 0; i < 7; i++) {
                    float2 tv = *reinterpret_cast<const float2*>(&Gb[(m0+i)*TPT + kk]);
                    u64 du0 = pk2(tv.x, tv.x);
                    u64 du1 = pk2(tv.y, tv.y);
                    #pragma unroll
                    for (int jp = 0; jp < 8; jp++) {
                        fma2(acc[i][jp], du0, bp[jp][0]);
                        fma2(acc[i][jp], du1, bp[jp][1]);
                    }
                }
            }
            #pragma unroll
            for (int i = 0; i < 7; i++) {
                u64* hr = reinterpret_cast<u64*>(&Hb[(m0+i)*HP + d0]);
                #pragma unroll
                for (int jp = 0; jp < 8; jp++) hr[jp] = acc[i][jp];
            }
        }
        __syncthreads();
    }

    // ---------------- stage 2: h2 = relu(x @ g2 + b2)  (regs, then overwrite Hb)
    {
        const int d0 = tc * 16;
        u64 acc[7][8];
        {
            u64 bb[8];
            #pragma unroll
            for (int jp = 0; jp < 8; jp++) bb[jp] = pk2(b2[d0+2*jp], b2[d0+2*jp+1]);
            #pragma unroll
            for (int i = 0; i < 7; i++)
                #pragma unroll
                for (int jp = 0; jp < 8; jp++) acc[i][jp] = bb[jp];
        }
        #pragma unroll 1
        for (int k = 0; k < NODE; k += 4) {
            float4 xv[7];
            #pragma unroll
            for (int i = 0; i < 7; i++) xv[i] = *reinterpret_cast<const float4*>(&xs[(m0+i)*XP + k]);
            #pragma unroll
            for (int kk = 0; kk < 4; kk++) {
                const u64* gr = reinterpret_cast<const u64*>(&Hb[(k+kk)*HP + d0]);
                u64 g[8];
                #pragma unroll
                for (int jp = 0; jp < 8; jp++) g[jp] = gr[jp];
                #pragma unroll
                for (int i = 0; i < 7; i++) {
                    float xk = (kk == 0) ? xv[i].x : (kk == 1) ? xv[i].y : (kk == 2) ? xv[i].z : xv[i].w;
                    u64 du = pk2(xk, xk);
                    #pragma unroll
                    for (int jp = 0; jp < 8; jp++) fma2(acc[i][jp], du, g[jp]);
                }
            }
        }
        __syncthreads();   // all g2 reads done before overwrite
        #pragma unroll
        for (int i = 0; i < 7; i++)
            #pragma unroll
            for (int jp = 0; jp < 8; jp++) {
                float2 v = up2(acc[i][jp]);
                Hb[(m0+i)*HP + d0 + 2*jp    ] = frelu(v.x);
                Hb[(m0+i)*HP + d0 + 2*jp + 1] = frelu(v.y);
            }
    }
    __syncthreads();

    // ---------------- stage 3: g3 = h2 @ W3^T  [112,128] -> Gb ------------------
    {
        const int d0 = tc * 8;
        u64 acc[7][4];
        #pragma unroll
        for (int i = 0; i < 7; i++)
            #pragma unroll
            for (int jp = 0; jp < 4; jp++) acc[i][jp] = 0ULL;
        #pragma unroll 1
        for (int k = 0; k < 256; k += 4) {
            u64 bp[4][4];
            #pragma unroll
            for (int jp = 0; jp < 4; jp++) {
                float4 a = *reinterpret_cast<const float4*>(W3 + (size_t)(d0+2*jp)*256 + k);
                float4 b = *reinterpret_cast<const float4*>(W3 + (size_t)(d0+2*jp+1)*256 + k);
                bp[jp][0] = pk2(a.x, b.x); bp[jp][1] = pk2(a.y, b.y);
                bp[jp][2] = pk2(a.z, b.z); bp[jp][3] = pk2(a.w, b.w);
            }
            #pragma unroll
            for (int i = 0; i < 7; i++) {
                float4 hv = *reinterpret_cast<const float4*>(&Hb[(m0+i)*HP + k]);
                u64 dx = pk2(hv.x, hv.x);
                u64 dy = pk2(hv.y, hv.y);
                u64 dz = pk2(hv.z, hv.z);
                u64 dw = pk2(hv.w, hv.w);
                #pragma unroll
                for (int jp = 0; jp < 4; jp++) {
                    fma2(acc[i][jp], dx, bp[jp][0]);
                    fma2(acc[i][jp], dy, bp[jp][1]);
                    fma2(acc[i][jp], dz, bp[jp][2]);
                    fma2(acc[i][jp], dw, bp[jp][3]);
                }
            }
        }
        #pragma unroll
        for (int i = 0; i < 7; i++)
            #pragma unroll
            for (int jp = 0; jp < 4; jp++) {
                float2 v = up2(acc[i][jp]);
                Gb[(m0+i)*GP3 + d0 + 2*jp    ] = v.x;
                Gb[(m0+i)*GP3 + d0 + 2*jp + 1] = v.y;
            }
    }
    __syncthreads();

    // ---------------- stage 4: h3 = relu(x @ g3 + b3) [112,128] -> Hb -----------
    {
        const int d0 = tc * 8;
        u64 acc[7][4];
        {
            u64 bb[4];
            #pragma unroll
            for (int jp = 0; jp < 4; jp++) bb[jp] = pk2(b3[d0+2*jp], b3[d0+2*jp+1]);
            #pragma unroll
            for (int i = 0; i < 7; i++)
                #pragma unroll
                for (int jp = 0; jp < 4; jp++) acc[i][jp] = bb[jp];
        }
        #pragma unroll 1
        for (int k = 0; k < NODE; k += 4) {
            float4 xv[7];
            #pragma unroll
            for (int i = 0; i < 7; i++) xv[i] = *reinterpret_cast<const float4*>(&xs[(m0+i)*XP + k]);
            #pragma unroll
            for (int kk = 0; kk < 4; kk++) {
                const u64* gr = reinterpret_cast<const u64*>(&Gb[(k+kk)*GP3 + d0]);
                u64 g[4];
                #pragma unroll
                for (int jp = 0; jp < 4; jp++) g[jp] = gr[jp];
                #pragma unroll
                for (int i = 0; i < 7; i++) {
                    float xk = (kk == 0) ? xv[i].x : (kk == 1) ? xv[i].y : (kk == 2) ? xv[i].z : xv[i].w;
                    u64 du = pk2(xk, xk);
                    #pragma unroll
                    for (int jp = 0; jp < 4; jp++) fma2(acc[i][jp], du, g[jp]);
                }
            }
        }
        #pragma unroll
        for (int i = 0; i < 7; i++)
            #pragma unroll
            for (int jp = 0; jp < 4; jp++) {
                float2 v = up2(acc[i][jp]);
                Hb[(m0+i)*HP + d0 + 2*jp    ] = frelu(v.x);
                Hb[(m0+i)*HP + d0 + 2*jp + 1] = frelu(v.y);
            }
    }
    __syncthreads();

    // ---------------- stage 5: g4 = h3 @ W4^T [112,64] -> Gb (pitch 68) ---------
    {
        const int d0 = tc * 4;
        u64 acc[7][2];
        #pragma unroll
        for (int i = 0; i < 7; i++) { acc[i][0] = 0ULL; acc[i][1] = 0ULL; }
        #pragma unroll 1
        for (int k = 0; k < 128; k += 4) {
            u64 bp[2][4];
            #pragma unroll
            for (int jp = 0; jp < 2; jp++) {
                float4 a = *reinterpret_cast<const float4*>(W4 + (size_t)(d0+2*jp)*128 + k);
                float4 b = *reinterpret_cast<const float4*>(W4 + (size_t)(d0+2*jp+1)*128 + k);
                bp[jp][0] = pk2(a.x, b.x); bp[jp][1] = pk2(a.y, b.y);
                bp[jp][2] = pk2(a.z, b.z); bp[jp][3] = pk2(a.w, b.w);
            }
            #pragma unroll
            for (int i = 0; i < 7; i++) {
                float4 hv = *reinterpret_cast<const float4*>(&Hb[(m0+i)*HP + k]);
                u64 dx = pk2(hv.x, hv.x);
                u64 dy = pk2(hv.y, hv.y);
                u64 dz = pk2(hv.z, hv.z);
                u64 dw = pk2(hv.w, hv.w);
                #pragma unroll
                for (int jp = 0; jp < 2; jp++) {
                    fma2(acc[i][jp], dx, bp[jp][0]);
                    fma2(acc[i][jp], dy, bp[jp][1]);
                    fma2(acc[i][jp], dz, bp[jp][2]);
                    fma2(acc[i][jp], dw, bp[jp][3]);
                }
            }
        }
        #pragma unroll
        for (int i = 0; i < 7; i++) {
            float2 v0 = up2(acc[i][0]), v1 = up2(acc[i][1]);
            float* g = &Gb[(m0+i)*TP2 + d0];
            g[0] = v0.x; g[1] = v0.y; g[2] = v1.x; g[3] = v1.y;
        }
    }
    __syncthreads();

    // ---------------- stage 6: h4 = relu(x @ g4 + b4) [112,64] -> Hb ------------
    {
        const int d0 = tc * 4;
        u64 acc[7][2];
        {
            u64 b0 = pk2(b4[d0], b4[d0+1]);
            u64 b1v = pk2(b4[d0+2], b4[d0+3]);
            #pragma unroll
            for (int i = 0; i < 7; i++) { acc[i][0] = b0; acc[i][1] = b1v; }
        }
        #pragma unroll 1
        for (int k = 0; k < NODE; k += 4) {
            float4 xv[7];
            #pragma unroll
            for (int i = 0; i < 7; i++) xv[i] = *reinterpret_cast<const float4*>(&xs[(m0+i)*XP + k]);
            #pragma unroll
            for (int kk = 0; kk < 4; kk++) {
                const u64* gr = reinterpret_cast<const u64*>(&Gb[(k+kk)*TP2 + d0]);
                u64 g0 = gr[0], g1 = gr[1];
                #pragma unroll
                for (int i = 0; i < 7; i++) {
                    float xk = (kk == 0) ? xv[i].x : (kk == 1) ? xv[i].y : (kk == 2) ? xv[i].z : xv[i].w;
                    u64 du = pk2(xk, xk);
                    fma2(acc[i][0], du, g0);
                    fma2(acc[i][1], du, g1);
                }
            }
        }
        #pragma unroll
        for (int i = 0; i < 7; i++) {
            float2 v0 = up2(acc[i][0]), v1 = up2(acc[i][1]);
            float* h = &Hb[(m0+i)*HP + d0];
            h[0] = frelu(v0.x); h[1] = frelu(v0.y);
            h[2] = frelu(v1.x); h[3] = frelu(v1.y);
        }
    }
    __syncthreads();

    // ---------------- stage 7: g5 = h4 @ W5^T  [112] ---------------------------
    if (tid < NODE) {
        float s = 0.f;
        #pragma unroll
        for (int c = 0; c < 64; c += 4) {
            float4 hv = *reinterpret_cast<const float4*>(&Hb[tid*HP + c]);
            float4 wv = *reinterpret_cast<const float4*>(W5 + c);
            s = fmaf(hv.x, wv.x, s);
            s = fmaf(hv.y, wv.y, s);
            s = fmaf(hv.z, wv.z, s);
            s = fmaf(hv.w, wv.w, s);
        }
        g5[tid] = s;
    }
    __syncthreads();

    // ---------------- stage 8: h5 = relu(x @ g5 + b5); partial products ---------
    if (tid < NODE) {
        float s = b5[0];
        #pragma unroll 4
        for (int m = 0; m < NODE; m++)
            s = fmaf(xs[tid*XP + m], g5[m], s);
        red[tid] = frelu(s) * Wf[tid];
    }
    __syncthreads();

    // ---------------- stage 9: out[b] = sum(red) + bf ---------------------------
    if (tid == 0) {
        float s = bf[0];
        #pragma unroll 4
        for (int n = 0; n < NODE; n++) s += red[n];
        out[bidx] = s;
    }
}

extern "C" void kernel_launch(void* const* d_in, const int* in_sizes, int n_in,
                              void* d_out, int out_size)
{
    const float* x  = (const float*)d_in[0];
    const float* W1 = (const float*)d_in[1];
    const float* b1 = (const float*)d_in[2];
    const float* W2 = (const float*)d_in[3];
    const float* b2 = (const float*)d_in[4];
    const float* W3 = (const float*)d_in[5];
    const float* b3 = (const float*)d_in[6];
    const float* W4 = (const float*)d_in[7];
    const float* b4 = (const float*)d_in[8];
    const float* W5 = (const float*)d_in[9];
    const float* b5 = (const float*)d_in[10];
    const float* Wf = (const float*)d_in[11];
    const float* bf = (const float*)d_in[12];
    float* out = (float*)d_out;

    const int batch = in_sizes[0] / (NODE * NODE);   // 4096

    cudaFuncSetAttribute(gcn_fused, cudaFuncAttributeMaxDynamicSharedMemorySize, SMEM_BYTES);
    gcn_fused<<<batch, TPB, SMEM_BYTES>>>(x, W1, b1, W2, b2, W3, b3, W4, b4,
                                          W5, b5, Wf, bf, out);
}

// round 8
// speedup vs baseline: 1.0019x; 1.0019x over previous
#include <cuda_runtime.h>

#define TPB 256
typedef unsigned long long u64;

namespace {
constexpr int NODE = 112;
constexpr int XP   = 116;   // x tile pitch (floats)
constexpr int HP   = 260;   // H buffer pitch (256 cols max)
constexpr int TPT  = 68;    // T (h1 block) pitch, 64 cols
constexpr int GP3  = 132;   // g3 pitch (128 cols)
constexpr int TP2  = 68;    // g4 pitch (64 cols)
constexpr int SMEM_FLOATS = NODE*XP + NODE*HP + NODE*GP3 + 256;
constexpr int SMEM_BYTES  = SMEM_FLOATS * 4;   // 228,608 B
}

__device__ __forceinline__ u64 pk2(float lo, float hi) {
    u64 r;
    asm("mov.b64 %0,{%1,%2};" : "=l"(r)
        : "r"(__float_as_uint(lo)), "r"(__float_as_uint(hi)));
    return r;
}
__device__ __forceinline__ void fma2(u64& d, u64 a, u64 b) {
    asm("fma.rn.f32x2 %0,%1,%2,%0;" : "+l"(d) : "l"(a), "l"(b));
}
__device__ __forceinline__ float2 up2(u64 p) {
    unsigned lo, hi;
    asm("mov.b64 {%0,%1},%2;" : "=r"(lo), "=r"(hi) : "l"(p));
    return make_float2(__uint_as_float(lo), __uint_as_float(hi));
}
__device__ __forceinline__ float frelu(float v) { return v > 0.f ? v : 0.f; }

__global__ __launch_bounds__(TPB, 1) void gcn_fused(
    const float* __restrict__ x,
    const float* __restrict__ W1, const float* __restrict__ b1,
    const float* __restrict__ W2, const float* __restrict__ b2,
    const float* __restrict__ W3, const float* __restrict__ b3,
    const float* __restrict__ W4, const float* __restrict__ b4,
    const float* __restrict__ W5, const float* __restrict__ b5,
    const float* __restrict__ Wf, const float* __restrict__ bf,
    float* __restrict__ out)
{
    extern __shared__ float sm[];
    float* xs  = sm;                    // [112][116]
    float* Hb  = sm + NODE*XP;          // [112][260]
    float* Gb  = Hb + NODE*HP;          // [112][132]  (T pitch 68 / g3 pitch 132 / g4 pitch 68)
    float* g5  = Gb + NODE*GP3;         // [112]
    float* red = g5 + NODE;             // [112]

    const int tid  = threadIdx.x;
    const int bidx = blockIdx.x;
    const int tr = tid & 15;
    const int tc = tid >> 4;
    const int m0 = tr * 7;

    // ---------------- stage 0: load x tile -------------------------------------
    {
        const float4* xg = reinterpret_cast<const float4*>(x + (size_t)bidx * NODE * NODE);
        #pragma unroll 4
        for (int i = tid; i < NODE * 28; i += TPB) {
            int r = i / 28, c = i - r * 28;
            *reinterpret_cast<float4*>(&xs[r*XP + c*4]) = xg[i];
        }
    }
    __syncthreads();

    // ---------------- stage 1: fused layer1 -> g2 = h1 @ W2^T ------------------
    // cb blocks of 64 h1-columns; T = relu(x@W1_blk^T + b1_blk) in Gb; g2 RMW in Hb.
    #pragma unroll 1
    for (int cb = 0; cb < 4; cb++) {
        const int c0 = cb * 64;
        // (a) T[112,64] block
        {
            const int d = c0 + tc * 4;
            const float* w0 = W1 + (size_t)d * NODE;
            const float* w1 = w0 + NODE;
            const float* w2 = w0 + 2*NODE;
            const float* w3 = w0 + 3*NODE;
            u64 a0[7], a1[7];
            {
                u64 bi0 = pk2(b1[d], b1[d+1]);
                u64 bi1 = pk2(b1[d+2], b1[d+3]);
                #pragma unroll
                for (int i = 0; i < 7; i++) { a0[i] = bi0; a1[i] = bi1; }
            }
            #pragma unroll 1
            for (int k = 0; k < NODE; k += 4) {
                float4 v0 = *reinterpret_cast<const float4*>(w0 + k);
                float4 v1 = *reinterpret_cast<const float4*>(w1 + k);
                float4 v2 = *reinterpret_cast<const float4*>(w2 + k);
                float4 v3 = *reinterpret_cast<const float4*>(w3 + k);
                u64 p00 = pk2(v0.x, v1.x), p01 = pk2(v0.y, v1.y);
                u64 p02 = pk2(v0.z, v1.z), p03 = pk2(v0.w, v1.w);
                u64 p10 = pk2(v2.x, v3.x), p11 = pk2(v2.y, v3.y);
                u64 p12 = pk2(v2.z, v3.z), p13 = pk2(v2.w, v3.w);
                #pragma unroll
                for (int i = 0; i < 7; i++) {
                    float4 xv = *reinterpret_cast<const float4*>(&xs[(m0+i)*XP + k]);
                    u64 dx = pk2(xv.x, xv.x);
                    u64 dy = pk2(xv.y, xv.y);
                    u64 dz = pk2(xv.z, xv.z);
                    u64 dw = pk2(xv.w, xv.w);
                    fma2(a0[i], dx, p00); fma2(a1[i], dx, p10);
                    fma2(a0[i], dy, p01); fma2(a1[i], dy, p11);
                    fma2(a0[i], dz, p02); fma2(a1[i], dz, p12);
                    fma2(a0[i], dw, p03); fma2(a1[i], dw, p13);
                }
            }
            #pragma unroll
            for (int i = 0; i < 7; i++) {
                float2 u = up2(a0[i]), v = up2(a1[i]);
                float* t = &Gb[(m0+i)*TPT + tc*4];
                t[0] = frelu(u.x); t[1] = frelu(u.y);
                t[2] = frelu(v.x); t[3] = frelu(v.y);
            }
        }
        __syncthreads();
        // (b) g2[:, d0:d0+16] += T @ W2[:, c0:c0+64]^T
        {
            const int d0 = tc * 16;
            u64 acc[7][8];
            if (cb == 0) {
                #pragma unroll
                for (int i = 0; i < 7; i++)
                    #pragma unroll
                    for (int jp = 0; jp < 8; jp++) acc[i][jp] = 0ULL;
            } else {
                #pragma unroll
                for (int i = 0; i < 7; i++) {
                    const u64* hr = reinterpret_cast<const u64*>(&Hb[(m0+i)*HP + d0]);
                    #pragma unroll
                    for (int jp = 0; jp < 8; jp++) acc[i][jp] = hr[jp];
                }
            }
            #pragma unroll 1
            for (int kk = 0; kk < 64; kk += 2) {
                u64 bp[8][2];
                #pragma unroll
                for (int jp = 0; jp < 8; jp++) {
                    const float* wa = W2 + (size_t)(d0 + 2*jp) * 256 + c0 + kk;
                    const float* wb = wa + 256;
                    float2 a = *reinterpret_cast<const float2*>(wa);
                    float2 b = *reinterpret_cast<const float2*>(wb);
                    bp[jp][0] = pk2(a.x, b.x);
                    bp[jp][1] = pk2(a.y, b.y);
                }
                #pragma unroll
                for (int i = 0; i < 7; i++) {
                    float2 tv = *reinterpret_cast<const float2*>(&Gb[(m0+i)*TPT + kk]);
                    u64 du0 = pk2(tv.x, tv.x);
                    u64 du1 = pk2(tv.y, tv.y);
                    #pragma unroll
                    for (int jp = 0; jp < 8; jp++) {
                        fma2(acc[i][jp], du0, bp[jp][0]);
                        fma2(acc[i][jp], du1, bp[jp][1]);
                    }
                }
            }
            #pragma unroll
            for (int i = 0; i < 7; i++) {
                u64* hr = reinterpret_cast<u64*>(&Hb[(m0+i)*HP + d0]);
                #pragma unroll
                for (int jp = 0; jp < 8; jp++) hr[jp] = acc[i][jp];
            }
        }
        __syncthreads();
    }

    // ---------------- stage 2: h2 = relu(x @ g2 + b2)  (regs, then overwrite Hb)
    {
        const int d0 = tc * 16;
        u64 acc[7][8];
        {
            u64 bb[8];
            #pragma unroll
            for (int jp = 0; jp < 8; jp++) bb[jp] = pk2(b2[d0+2*jp], b2[d0+2*jp+1]);
            #pragma unroll
            for (int i = 0; i < 7; i++)
                #pragma unroll
                for (int jp = 0; jp < 8; jp++) acc[i][jp] = bb[jp];
        }
        #pragma unroll 1
        for (int k = 0; k < NODE; k += 4) {
            float4 xv[7];
            #pragma unroll
            for (int i = 0; i < 7; i++) xv[i] = *reinterpret_cast<const float4*>(&xs[(m0+i)*XP + k]);
            #pragma unroll
            for (int kk = 0; kk < 4; kk++) {
                const u64* gr = reinterpret_cast<const u64*>(&Hb[(k+kk)*HP + d0]);
                u64 g[8];
                #pragma unroll
                for (int jp = 0; jp < 8; jp++) g[jp] = gr[jp];
                #pragma unroll
                for (int i = 0; i < 7; i++) {
                    float xk = (kk == 0) ? xv[i].x : (kk == 1) ? xv[i].y : (kk == 2) ? xv[i].z : xv[i].w;
                    u64 du = pk2(xk, xk);
                    #pragma unroll
                    for (int jp = 0; jp < 8; jp++) fma2(acc[i][jp], du, g[jp]);
                }
            }
        }
        __syncthreads();   // all g2 reads done before overwrite
        #pragma unroll
        for (int i = 0; i < 7; i++)
            #pragma unroll
            for (int jp = 0; jp < 8; jp++) {
                float2 v = up2(acc[i][jp]);
                Hb[(m0+i)*HP + d0 + 2*jp    ] = frelu(v.x);
                Hb[(m0+i)*HP + d0 + 2*jp + 1] = frelu(v.y);
            }
    }
    __syncthreads();

    // ---------------- stage 3: g3 = h2 @ W3^T  [112,128] -> Gb ------------------
    {
        const int d0 = tc * 8;
        u64 acc[7][4];
        #pragma unroll
        for (int i = 0; i < 7; i++)
            #pragma unroll
            for (int jp = 0; jp < 4; jp++) acc[i][jp] = 0ULL;
        #pragma unroll 1
        for (int k = 0; k < 256; k += 4) {
            u64 bp[4][4];
            #pragma unroll
            for (int jp = 0; jp < 4; jp++) {
                float4 a = *reinterpret_cast<const float4*>(W3 + (size_t)(d0+2*jp)*256 + k);
                float4 b = *reinterpret_cast<const float4*>(W3 + (size_t)(d0+2*jp+1)*256 + k);
                bp[jp][0] = pk2(a.x, b.x); bp[jp][1] = pk2(a.y, b.y);
                bp[jp][2] = pk2(a.z, b.z); bp[jp][3] = pk2(a.w, b.w);
            }
            #pragma unroll
            for (int i = 0; i < 7; i++) {
                float4 hv = *reinterpret_cast<const float4*>(&Hb[(m0+i)*HP + k]);
                u64 dx = pk2(hv.x, hv.x);
                u64 dy = pk2(hv.y, hv.y);
                u64 dz = pk2(hv.z, hv.z);
                u64 dw = pk2(hv.w, hv.w);
                #pragma unroll
                for (int jp = 0; jp < 4; jp++) {
                    fma2(acc[i][jp], dx, bp[jp][0]);
                    fma2(acc[i][jp], dy, bp[jp][1]);
                    fma2(acc[i][jp], dz, bp[jp][2]);
                    fma2(acc[i][jp], dw, bp[jp][3]);
                }
            }
        }
        #pragma unroll
        for (int i = 0; i < 7; i++)
            #pragma unroll
            for (int jp = 0; jp < 4; jp++) {
                float2 v = up2(acc[i][jp]);
                Gb[(m0+i)*GP3 + d0 + 2*jp    ] = v.x;
                Gb[(m0+i)*GP3 + d0 + 2*jp + 1] = v.y;
            }
    }
    __syncthreads();

    // ---------------- stage 4: h3 = relu(x @ g3 + b3) [112,128] -> Hb -----------
    {
        const int d0 = tc * 8;
        u64 acc[7][4];
        {
            u64 bb[4];
            #pragma unroll
            for (int jp = 0; jp < 4; jp++) bb[jp] = pk2(b3[d0+2*jp], b3[d0+2*jp+1]);
            #pragma unroll
            for (int i = 0; i < 7; i++)
                #pragma unroll
                for (int jp = 0; jp < 4; jp++) acc[i][jp] = bb[jp];
        }
        #pragma unroll 1
        for (int k = 0; k < NODE; k += 4) {
            float4 xv[7];
            #pragma unroll
            for (int i = 0; i < 7; i++) xv[i] = *reinterpret_cast<const float4*>(&xs[(m0+i)*XP + k]);
            #pragma unroll
            for (int kk = 0; kk < 4; kk++) {
                const u64* gr = reinterpret_cast<const u64*>(&Gb[(k+kk)*GP3 + d0]);
                u64 g[4];
                #pragma unroll
                for (int jp = 0; jp < 4; jp++) g[jp] = gr[jp];
                #pragma unroll
                for (int i = 0; i < 7; i++) {
                    float xk = (kk == 0) ? xv[i].x : (kk == 1) ? xv[i].y : (kk == 2) ? xv[i].z : xv[i].w;
                    u64 du = pk2(xk, xk);
                    #pragma unroll
                    for (int jp = 0; jp < 4; jp++) fma2(acc[i][jp], du, g[jp]);
                }
            }
        }
        #pragma unroll
        for (int i = 0; i < 7; i++)
            #pragma unroll
            for (int jp = 0; jp < 4; jp++) {
                float2 v = up2(acc[i][jp]);
                Hb[(m0+i)*HP + d0 + 2*jp    ] = frelu(v.x);
                Hb[(m0+i)*HP + d0 + 2*jp + 1] = frelu(v.y);
            }
    }
    __syncthreads();

    // ---------------- stage 5: g4 = h3 @ W4^T [112,64] -> Gb (pitch 68) ---------
    {
        const int d0 = tc * 4;
        u64 acc[7][2];
        #pragma unroll
        for (int i = 0; i < 7; i++) { acc[i][0] = 0ULL; acc[i][1] = 0ULL; }
        #pragma unroll 1
        for (int k = 0; k < 128; k += 4) {
            u64 bp[2][4];
            #pragma unroll
            for (int jp = 0; jp < 2; jp++) {
                float4 a = *reinterpret_cast<const float4*>(W4 + (size_t)(d0+2*jp)*128 + k);
                float4 b = *reinterpret_cast<const float4*>(W4 + (size_t)(d0+2*jp+1)*128 + k);
                bp[jp][0] = pk2(a.x, b.x); bp[jp][1] = pk2(a.y, b.y);
                bp[jp][2] = pk2(a.z, b.z); bp[jp][3] = pk2(a.w, b.w);
            }
            #pragma unroll
            for (int i = 0; i < 7; i++) {
                float4 hv = *reinterpret_cast<const float4*>(&Hb[(m0+i)*HP + k]);
                u64 dx = pk2(hv.x, hv.x);
                u64 dy = pk2(hv.y, hv.y);
                u64 dz = pk2(hv.z, hv.z);
                u64 dw = pk2(hv.w, hv.w);
                #pragma unroll
                for (int jp = 0; jp < 2; jp++) {
                    fma2(acc[i][jp], dx, bp[jp][0]);
                    fma2(acc[i][jp], dy, bp[jp][1]);
                    fma2(acc[i][jp], dz, bp[jp][2]);
                    fma2(acc[i][jp], dw, bp[jp][3]);
                }
            }
        }
        #pragma unroll
        for (int i = 0; i < 7; i++) {
            float2 v0 = up2(acc[i][0]), v1 = up2(acc[i][1]);
            float* g = &Gb[(m0+i)*TP2 + d0];
            g[0] = v0.x; g[1] = v0.y; g[2] = v1.x; g[3] = v1.y;
        }
    }
    __syncthreads();

    // ---------------- stage 6: h4 = relu(x @ g4 + b4) [112,64] -> Hb ------------
    {
        const int d0 = tc * 4;
        u64 acc[7][2];
        {
            u64 b0 = pk2(b4[d0], b4[d0+1]);
            u64 b1v = pk2(b4[d0+2], b4[d0+3]);
            #pragma unroll
            for (int i = 0; i < 7; i++) { acc[i][0] = b0; acc[i][1] = b1v; }
        }
        #pragma unroll 1
        for (int k = 0; k < NODE; k += 4) {
            float4 xv[7];
            #pragma unroll
            for (int i = 0; i < 7; i++) xv[i] = *reinterpret_cast<const float4*>(&xs[(m0+i)*XP + k]);
            #pragma unroll
            for (int kk = 0; kk < 4; kk++) {
                const u64* gr = reinterpret_cast<const u64*>(&Gb[(k+kk)*TP2 + d0]);
                u64 g0 = gr[0], g1 = gr[1];
                #pragma unroll
                for (int i = 0; i < 7; i++) {
                    float xk = (kk == 0) ? xv[i].x : (kk == 1) ? xv[i].y : (kk == 2) ? xv[i].z : xv[i].w;
                    u64 du = pk2(xk, xk);
                    fma2(acc[i][0], du, g0);
                    fma2(acc[i][1], du, g1);
                }
            }
        }
        #pragma unroll
        for (int i = 0; i < 7; i++) {
            float2 v0 = up2(acc[i][0]), v1 = up2(acc[i][1]);
            float* h = &Hb[(m0+i)*HP + d0];
            h[0] = frelu(v0.x); h[1] = frelu(v0.y);
            h[2] = frelu(v1.x); h[3] = frelu(v1.y);
        }
    }
    __syncthreads();

    // ---------------- stage 7: g5 = h4 @ W5^T  [112] ---------------------------
    if (tid < NODE) {
        float s = 0.f;
        #pragma unroll
        for (int c = 0; c < 64; c += 4) {
            float4 hv = *reinterpret_cast<const float4*>(&Hb[tid*HP + c]);
            float4 wv = *reinterpret_cast<const float4*>(W5 + c);
            s = fmaf(hv.x, wv.x, s);
            s = fmaf(hv.y, wv.y, s);
            s = fmaf(hv.z, wv.z, s);
            s = fmaf(hv.w, wv.w, s);
        }
        g5[tid] = s;
    }
    __syncthreads();

    // ---------------- stage 8: h5 = relu(x @ g5 + b5); partial products ---------
    if (tid < NODE) {
        float s = b5[0];
        #pragma unroll 4
        for (int m = 0; m < NODE; m++)
            s = fmaf(xs[tid*XP + m], g5[m], s);
        red[tid] = frelu(s) * Wf[tid];
    }
    __syncthreads();

    // ---------------- stage 9: out[b] = sum(red) + bf ---------------------------
    if (tid == 0) {
        float s = bf[0];
        #pragma unroll 4
        for (int n = 0; n < NODE; n++) s += red[n];
        out[bidx] = s;
    }
}

extern "C" void kernel_launch(void* const* d_in, const int* in_sizes, int n_in,
                              void* d_out, int out_size)
{
    const float* x  = (const float*)d_in[0];
    const float* W1 = (const float*)d_in[1];
    const float* b1 = (const float*)d_in[2];
    const float* W2 = (const float*)d_in[3];
    const float* b2 = (const float*)d_in[4];
    const float* W3 = (const float*)d_in[5];
    const float* b3 = (const float*)d_in[6];
    const float* W4 = (const float*)d_in[7];
    const float* b4 = (const float*)d_in[8];
    const float* W5 = (const float*)d_in[9];
    const float* b5 = (const float*)d_in[10];
    const float* Wf = (const float*)d_in[11];
    const float* bf = (const float*)d_in[12];
    float* out = (float*)d_out;

    const int batch = in_sizes[0] / (NODE * NODE);   // 4096

    cudaFuncSetAttribute(gcn_fused, cudaFuncAttributeMaxDynamicSharedMemorySize, SMEM_BYTES);
    gcn_fused<<<batch, TPB, SMEM_BYTES>>>(x, W1, b1, W2, b2, W3, b3, W4, b4,
                                          W5, b5, Wf, bf, out);
}

// round 11
// speedup vs baseline: 2.5300x; 2.5253x over previous
#include <cuda_runtime.h>
#include <cstdint>

#define TPB 256
// pitches / offsets (bytes)
#define PX   464
#define PW2  1040
#define PW4  528
#define PC   264
#define CSTR 29696
#define OFF_G5  0
#define OFF_RED 512
#define OFF_X   1024
#define OFF_G   52992
#define OFF_R2  171776
#define SMEM_BYTES 231168

__device__ __align__(16) unsigned char W1S[256 * PX];
__device__ __align__(16) unsigned char W2S[256 * PW2];
__device__ __align__(16) unsigned char W3S[128 * PW2];
__device__ __align__(16) unsigned char W4S[64 * PW4];

__device__ __forceinline__ uint32_t f2bf(float f) {
    uint32_t u = __float_as_uint(f);
    return (u + 0x7FFFu + ((u >> 16) & 1u)) >> 16;
}
__device__ __forceinline__ float bf2f(uint32_t b) { return __uint_as_float(b << 16); }
__device__ __forceinline__ int bo(int k) { return ((k >> 4) << 6) + ((k & 15) << 1); }

// ---------------- prep: weights -> blocked hi/lo bf16 scratch ----------------
__global__ void gcn_prep(const float* __restrict__ W1, const float* __restrict__ W2,
                         const float* __restrict__ W3, const float* __restrict__ W4)
{
    for (int i = blockIdx.x * blockDim.x + threadIdx.x; i < 135168;
         i += gridDim.x * blockDim.x) {
        int t = i, n, k, pitch; float v; unsigned char* dst;
        if (t < 28672)            { n = t / 112; k = t % 112; v = W1[n*112+k]; dst = W1S; pitch = PX;  }
        else if ((t -= 28672) < 65536) { n = t >> 8; k = t & 255; v = W2[n*256+k]; dst = W2S; pitch = PW2; }
        else if ((t -= 65536) < 32768) { n = t >> 8; k = t & 255; v = W3[n*256+k]; dst = W3S; pitch = PW2; }
        else { t -= 32768;          n = t >> 7; k = t & 127; v = W4[n*128+k]; dst = W4S; pitch = PW4; }
        uint32_t h = f2bf(v);
        unsigned char* p = dst + n * pitch + bo(k);
        *(unsigned short*)p        = (unsigned short)h;
        *(unsigned short*)(p + 32) = (unsigned short)f2bf(v - bf2f(h));
    }
}

// ---------------- mma + fragment helpers ----------------
__device__ __forceinline__ void mma(float* c, const uint32_t* a, const uint32_t* b) {
    asm volatile("mma.sync.aligned.m16n8k16.row.col.f32.bf16.bf16.f32 "
        "{%0,%1,%2,%3},{%4,%5,%6,%7},{%8,%9},{%0,%1,%2,%3};"
        : "+f"(c[0]), "+f"(c[1]), "+f"(c[2]), "+f"(c[3])
        : "r"(a[0]), "r"(a[1]), "r"(a[2]), "r"(a[3]), "r"(b[0]), "r"(b[1]));
}
__device__ __forceinline__ void ldA(uint32_t* a, const unsigned char* base, int pitch, int g, int t) {
    const unsigned char* p = base + g * pitch + 4 * t;
    a[0] = *(const uint32_t*)p; a[2] = *(const uint32_t*)(p + 16);
    p += 8 * pitch;
    a[1] = *(const uint32_t*)p; a[3] = *(const uint32_t*)(p + 16);
}
__device__ __forceinline__ void ldB(uint32_t* b, const unsigned char* base, int pitch, int g, int t) {
    const unsigned char* p = base + g * pitch + 4 * t;
    b[0] = *(const uint32_t*)p; b[1] = *(const uint32_t*)(p + 16);
}
__device__ __forceinline__ void st_hl(unsigned char* p, float v0, float v1) {
    uint32_t h0 = f2bf(v0), h1 = f2bf(v1);
    *(uint32_t*)p = h0 | (h1 << 16);
    *(uint32_t*)(p + 32) = f2bf(v0 - bf2f(h0)) | (f2bf(v1 - bf2f(h1)) << 16);
}
__device__ __forceinline__ void stT(unsigned char* base, int n, int k, float v) {
    unsigned char* p = base + n * PX + bo(k);
    uint32_t h = f2bf(v);
    *(unsigned short*)p        = (unsigned short)h;
    *(unsigned short*)(p + 32) = (unsigned short)f2bf(v - bf2f(h));
}

// aggregation: h-chunks = relu(x @ gT + bias), in place over gT chunks
__device__ __forceinline__ void agg_run(unsigned char* sm, unsigned char* region,
                                        int nchunks, const float* bias,
                                        int w, int g, int t)
{
    #pragma unroll 1
    for (int c = 0; c < nchunks; c++) {
        unsigned char* cbase = region + c * CSTR;
        float CC[32];
        if (w < 7) {
            #pragma unroll
            for (int i = 0; i < 32; i++) CC[i] = 0.f;
            #pragma unroll 1
            for (int s = 0; s < 7; s++) {
                uint32_t Ah[4], Al[4];
                const unsigned char* ab = sm + OFF_X + w * 16 * PX + s * 64;
                ldA(Ah, ab, PX, g, t); ldA(Al, ab + 32, PX, g, t);
                #pragma unroll
                for (int nt = 0; nt < 8; nt++) {
                    uint32_t Bh[2], Bl[2];
                    const unsigned char* gb = cbase + nt * 8 * PX + s * 64;
                    ldB(Bh, gb, PX, g, t); ldB(Bl, gb + 32, PX, g, t);
                    mma(&CC[nt*4], Ah, Bh); mma(&CC[nt*4], Ah, Bl); mma(&CC[nt*4], Al, Bh);
                }
            }
        }
        __syncthreads();
        if (w < 7) {
            #pragma unroll
            for (int nt = 0; nt < 8; nt++) {
                int f = nt * 8 + 2 * t;
                float bb0 = bias[c*64 + f], bb1 = bias[c*64 + f + 1];
                float v0 = fmaxf(CC[nt*4+0] + bb0, 0.f), v1 = fmaxf(CC[nt*4+1] + bb1, 0.f);
                float v2 = fmaxf(CC[nt*4+2] + bb0, 0.f), v3 = fmaxf(CC[nt*4+3] + bb1, 0.f);
                unsigned char* p0 = cbase + (w * 16 + g) * PC + bo(f);
                st_hl(p0, v0, v1);
                st_hl(p0 + 8 * PC, v2, v3);
            }
        }
        __syncthreads();
    }
}

// projection: gT_out = (A_chunked @ W^T)^T   (no bias/relu)
template <int NTW>
__device__ __forceinline__ void proj_run(unsigned char* sm, const unsigned char* Aregion,
                                         int nsteps, const unsigned char* Wg, int wpitch,
                                         unsigned char* outGT, int w, int g, int t)
{
    float CP[7 * NTW * 4];
    #pragma unroll
    for (int i = 0; i < 7 * NTW * 4; i++) CP[i] = 0.f;
    #pragma unroll 1
    for (int s = 0; s < nsteps; s++) {
        uint32_t Bh[NTW][2], Bl[NTW][2];
        #pragma unroll
        for (int nt = 0; nt < NTW; nt++) {
            const unsigned char* wb = Wg + (size_t)(w * NTW * 8 + nt * 8) * wpitch + s * 64;
            ldB(Bh[nt], wb, wpitch, g, t); ldB(Bl[nt], wb + 32, wpitch, g, t);
        }
        #pragma unroll
        for (int mt = 0; mt < 7; mt++) {
            uint32_t Ah[4], Al[4];
            const unsigned char* ab = Aregion + (s >> 2) * CSTR + mt * 16 * PC + (s & 3) * 64;
            ldA(Ah, ab, PC, g, t); ldA(Al, ab + 32, PC, g, t);
            #pragma unroll
            for (int nt = 0; nt < NTW; nt++) {
                float* c = &CP[(mt * NTW + nt) * 4];
                mma(c, Ah, Bh[nt]); mma(c, Ah, Bl[nt]); mma(c, Al, Bh[nt]);
            }
        }
    }
    __syncthreads();
    #pragma unroll
    for (int mt = 0; mt < 7; mt++)
        #pragma unroll
        for (int nt = 0; nt < NTW; nt++) {
            float* c = &CP[(mt * NTW + nt) * 4];
            int n0 = w * NTW * 8 + nt * 8 + 2 * t, m = mt * 16 + g;
            stT(outGT, n0, m, c[0]);     stT(outGT, n0 + 1, m, c[1]);
            stT(outGT, n0, m + 8, c[2]); stT(outGT, n0 + 1, m + 8, c[3]);
        }
    __syncthreads();
}

// ---------------- main kernel ----------------
__global__ __launch_bounds__(TPB, 1) void gcn_mma(
    const float* __restrict__ x,
    const float* __restrict__ b1, const float* __restrict__ b2,
    const float* __restrict__ b3, const float* __restrict__ b4,
    const float* __restrict__ W5, const float* __restrict__ b5,
    const float* __restrict__ Wf, const float* __restrict__ bf,
    float* __restrict__ out)
{
    extern __shared__ unsigned char sm[];
    const int tid = threadIdx.x, w = tid >> 5, lane = tid & 31;
    const int g = lane >> 2, t = lane & 3;
    const int bidx = blockIdx.x;

    // stage 0: x -> blocked hi/lo bf16
    if (tid < 112) {
        const float* gx = x + (size_t)bidx * 12544 + (size_t)tid * 112;
        unsigned char* row = sm + OFF_X + tid * PX;
        #pragma unroll
        for (int blk = 0; blk < 7; blk++) {
            float f[16];
            #pragma unroll
            for (int q = 0; q < 4; q++) {
                float4 v = *(const float4*)(gx + blk * 16 + q * 4);
                f[q*4] = v.x; f[q*4+1] = v.y; f[q*4+2] = v.z; f[q*4+3] = v.w;
            }
            uint32_t H[8], L[8];
            #pragma unroll
            for (int q = 0; q < 8; q++) {
                uint32_t h0 = f2bf(f[q*2]), h1 = f2bf(f[q*2+1]);
                H[q] = h0 | (h1 << 16);
                L[q] = f2bf(f[q*2] - bf2f(h0)) | (f2bf(f[q*2+1] - bf2f(h1)) << 16);
            }
            *(uint4*)(row + blk*64)      = make_uint4(H[0], H[1], H[2], H[3]);
            *(uint4*)(row + blk*64 + 16) = make_uint4(H[4], H[5], H[6], H[7]);
            *(uint4*)(row + blk*64 + 32) = make_uint4(L[0], L[1], L[2], L[3]);
            *(uint4*)(row + blk*64 + 48) = make_uint4(L[4], L[5], L[6], L[7]);
        }
    }
    __syncthreads();

    // P1/P2 fused: g2T = (relu(x@W1^T+b1) @ W2^T)^T, accumulated in registers
    {
        float C2[112];
        #pragma unroll
        for (int i = 0; i < 112; i++) C2[i] = 0.f;

        #pragma unroll 1
        for (int cb = 0; cb < 4; cb++) {
            // T = relu(x @ W1[cb*64:+64]^T + b1)  -> OFF_R2 chunk layout
            if (w < 7) {
                float CT[32];
                #pragma unroll
                for (int i = 0; i < 32; i++) CT[i] = 0.f;
                #pragma unroll 1
                for (int s = 0; s < 7; s++) {
                    uint32_t Ah[4], Al[4];
                    const unsigned char* ab = sm + OFF_X + w * 16 * PX + s * 64;
                    ldA(Ah, ab, PX, g, t); ldA(Al, ab + 32, PX, g, t);
                    #pragma unroll
                    for (int nt = 0; nt < 8; nt++) {
                        uint32_t Bh[2], Bl[2];
                        const unsigned char* wb = W1S + (size_t)(cb * 64 + nt * 8) * PX + s * 64;
                        ldB(Bh, wb, PX, g, t); ldB(Bl, wb + 32, PX, g, t);
                        mma(&CT[nt*4], Ah, Bh); mma(&CT[nt*4], Ah, Bl); mma(&CT[nt*4], Al, Bh);
                    }
                }
                #pragma unroll
                for (int nt = 0; nt < 8; nt++) {
                    int f = nt * 8 + 2 * t;
                    float bb0 = b1[cb*64 + f], bb1 = b1[cb*64 + f + 1];
                    float v0 = fmaxf(CT[nt*4+0] + bb0, 0.f), v1 = fmaxf(CT[nt*4+1] + bb1, 0.f);
                    float v2 = fmaxf(CT[nt*4+2] + bb0, 0.f), v3 = fmaxf(CT[nt*4+3] + bb1, 0.f);
                    unsigned char* p0 = sm + OFF_R2 + (w * 16 + g) * PC + bo(f);
                    st_hl(p0, v0, v1);
                    st_hl(p0 + 8 * PC, v2, v3);
                }
            }
            __syncthreads();
            // C2 += T @ W2[:, cb*64:+64]^T   (warp owns g2 cols [32w,32w+32))
            #pragma unroll 1
            for (int s = 0; s < 4; s++) {
                uint32_t Bh[4][2], Bl[4][2];
                #pragma unroll
                for (int nt = 0; nt < 4; nt++) {
                    const unsigned char* wb = W2S + (size_t)(w * 32 + nt * 8) * PW2 + (cb * 4 + s) * 64;
                    ldB(Bh[nt], wb, PW2, g, t); ldB(Bl[nt], wb + 32, PW2, g, t);
                }
                #pragma unroll
                for (int mt = 0; mt < 7; mt++) {
                    uint32_t Ah[4], Al[4];
                    const unsigned char* ab = sm + OFF_R2 + mt * 16 * PC + s * 64;
                    ldA(Ah, ab, PC, g, t); ldA(Al, ab + 32, PC, g, t);
                    #pragma unroll
                    for (int nt = 0; nt < 4; nt++) {
                        float* c = &C2[(mt * 4 + nt) * 4];
                        mma(c, Ah, Bh[nt]); mma(c, Ah, Bl[nt]); mma(c, Al, Bh[nt]);
                    }
                }
            }
            __syncthreads();
        }
        // write g2T (transposed) into OFF_G
        #pragma unroll
        for (int mt = 0; mt < 7; mt++)
            #pragma unroll
            for (int nt = 0; nt < 4; nt++) {
                float* c = &C2[(mt * 4 + nt) * 4];
                int n0 = w * 32 + nt * 8 + 2 * t, m = mt * 16 + g;
                stT(sm + OFF_G, n0, m, c[0]);     stT(sm + OFF_G, n0 + 1, m, c[1]);
                stT(sm + OFF_G, n0, m + 8, c[2]); stT(sm + OFF_G, n0 + 1, m + 8, c[3]);
            }
    }
    __syncthreads();

    agg_run(sm, sm + OFF_G, 4, b2, w, g, t);                          // h2 (in place)
    proj_run<2>(sm, sm + OFF_G, 16, W3S, PW2, sm + OFF_R2, w, g, t);  // g3T
    agg_run(sm, sm + OFF_R2, 2, b3, w, g, t);                         // h3 (in place)
    proj_run<1>(sm, sm + OFF_R2, 8, W4S, PW4, sm + OFF_G, w, g, t);   // g4T
    agg_run(sm, sm + OFF_G, 1, b4, w, g, t);                          // h4 (in place)

    // tail: g5 = h4 @ W5^T ; h5 = relu(x@g5+b5) ; out = sum(h5*Wf)+bf
    if (tid < 112) {
        const unsigned char* hr = sm + OFF_G + tid * PC;
        float s = 0.f;
        #pragma unroll
        for (int f = 0; f < 64; f++) {
            uint32_t hv = *(const unsigned short*)(hr + bo(f));
            uint32_t lv = *(const unsigned short*)(hr + bo(f) + 32);
            s = fmaf(bf2f(hv) + bf2f(lv), W5[f], s);
        }
        ((float*)(sm + OFF_G5))[tid] = s;
    }
    __syncthreads();
    if (tid < 112) {
        const float* g5 = (const float*)(sm + OFF_G5);
        const unsigned char* xr = sm + OFF_X + tid * PX;
        float s = b5[0];
        #pragma unroll 4
        for (int m = 0; m < 112; m++) {
            uint32_t hv = *(const unsigned short*)(xr + bo(m));
            uint32_t lv = *(const unsigned short*)(xr + bo(m) + 32);
            s = fmaf(bf2f(hv) + bf2f(lv), g5[m], s);
        }
        ((float*)(sm + OFF_RED))[tid] = fmaxf(s, 0.f) * Wf[tid];
    }
    __syncthreads();
    if (tid == 0) {
        const float* rd = (const float*)(sm + OFF_RED);
        float s = bf[0];
        #pragma unroll 4
        for (int n = 0; n < 112; n++) s += rd[n];
        out[bidx] = s;
    }
}

extern "C" void kernel_launch(void* const* d_in, const int* in_sizes, int n_in,
                              void* d_out, int out_size)
{
    const float* x  = (const float*)d_in[0];
    const float* W1 = (const float*)d_in[1];
    const float* b1 = (const float*)d_in[2];
    const float* W2 = (const float*)d_in[3];
    const float* b2 = (const float*)d_in[4];
    const float* W3 = (const float*)d_in[5];
    const float* b3 = (const float*)d_in[6];
    const float* W4 = (const float*)d_in[7];
    const float* b4 = (const float*)d_in[8];
    const float* W5 = (const float*)d_in[9];
    const float* b5 = (const float*)d_in[10];
    const float* Wf = (const float*)d_in[11];
    const float* bf = (const float*)d_in[12];
    float* out = (float*)d_out;

    const int batch = in_sizes[0] / (112 * 112);

    gcn_prep<<<132, 256>>>(W1, W2, W3, W4);

    cudaFuncSetAttribute(gcn_mma, cudaFuncAttributeMaxDynamicSharedMemorySize, SMEM_BYTES);
    gcn_mma<<<batch, TPB, SMEM_BYTES>>>(x, b1, b2, b3, b4, W5, b5, Wf, bf, out);
}